// round 16
// baseline (speedup 1.0000x reference)
#include <cuda_runtime.h>
#include <cuda_fp16.h>
#include <math.h>
#include <stdint.h>

#define T_TOK 1024
#define H_DIM 2048
#define I_DIM 768
#define E_NUM 32
#define K_TOP 8

#define BM 128
#define BN 64
#define DN_BN 128
#define BK 32
#define RSB 80
#define ASTAGES 6

#define A_STG    (BM * RSB)                 // 10240
#define GU_SLABB (2 * BN * RSB)             // 10240
#define GU_PBUF  (2 * GU_SLABB)             // 20480
#define GU_DEST  (ASTAGES * A_STG)          // 61440
#define DN_SLABB (DN_BN * RSB)
#define DN_PBUF  (2 * DN_SLABB)
#define DN_DEST  (ASTAGES * A_STG)
#define MOE_SMEM 102400

#define GU_NC (H_DIM / BK)
#define GU_NP (GU_NC / 2)                   // 32
#define DN_NC (I_DIM / BK)
#define DN_NP (DN_NC / 2)                   // 12

#define GU_XT (T_TOK / BM)                  // 8
#define GU_YT (I_DIM / BN)                  // 12
#define DN_YT (H_DIM / DN_BN)               // 16
#define GU_PER_E (GU_XT * GU_YT)            // 96
#define DN_PER_E (GU_XT * DN_YT)            // 128

// queue layout: converts | gateup | down | reduce
#define CV_PER_E   48                       // 16 gw + 16 uw + 16 dw chunks
#define CV_ITEMS   (CV_PER_E * E_NUM)       // 1536
#define GU_ITEMS   (GU_PER_E * E_NUM)       // 3072
#define DN_ITEMS   (DN_PER_E * E_NUM)       // 4096
#define RD_ITEMS   T_TOK                    // 1024
#define GU_BASE    CV_ITEMS
#define DN_BASE    (GU_BASE + GU_ITEMS)
#define RD_BASE    (DN_BASE + DN_ITEMS)
#define TOT_ITEMS  (RD_BASE + RD_ITEMS)

#define W_PER_E    (I_DIM * H_DIM)          // 1572864 floats per expert per matrix
#define CV_CHUNK   (W_PER_E / 16)           // 98304 floats per convert item

// ---------------- scratch ----------------
__device__ int    g_cnt[E_NUM];
__device__ int    g_off[E_NUM + 1];
__device__ int    g_list_tok[E_NUM * T_TOK];
__device__ float  g_list_w[E_NUM * T_TOK];
__device__ int    g_list_tk[E_NUM * T_TOK];
__device__ int    g_slot_of[T_TOK * K_TOP];
__device__ __half g_act[(size_t)T_TOK * K_TOP * I_DIM];
__device__ __half g_pair[(size_t)T_TOK * K_TOP * H_DIM];
__device__ __half g_xh[(size_t)T_TOK * H_DIM];
__device__ __half g_gw16[(size_t)E_NUM * W_PER_E];
__device__ __half g_uw16[(size_t)E_NUM * W_PER_E];
__device__ __half g_dw16[(size_t)E_NUM * W_PER_E];
__device__ int    g_work;
__device__ int    g_done[E_NUM];
__device__ int    g_cvg[E_NUM];
__device__ int    g_cvd[E_NUM];
__device__ int    g_dn_all;

__global__ void zero_cnt_kernel() {
    if (threadIdx.x < E_NUM) {
        g_cnt[threadIdx.x] = 0; g_done[threadIdx.x] = 0;
        g_cvg[threadIdx.x] = 0; g_cvd[threadIdx.x] = 0;
    }
    if (threadIdx.x == 0) { g_work = 0; g_dn_all = 0; }
}

// ---------------- router (+ fp16 copy of x) ----------------
__global__ void router_kernel(const float* __restrict__ x,
                              const float* __restrict__ gate_w,
                              float* __restrict__ logits_out) {
    const int TPB = 4;
    __shared__ float xs[TPB][H_DIM];
    __shared__ float lg[TPB][E_NUM];

    int t0 = blockIdx.x * TPB;
    const float4* xv  = (const float4*)(x + (size_t)t0 * H_DIM);
    float4*       xsv = (float4*)&xs[0][0];
    for (int i = threadIdx.x; i < TPB * H_DIM / 4; i += blockDim.x) xsv[i] = xv[i];
    __syncthreads();

    {
        const float* xf = &xs[0][0];
        __half2* dst = (__half2*)(g_xh + (size_t)t0 * H_DIM);
        for (int i = threadIdx.x; i < TPB * H_DIM / 2; i += blockDim.x)
            dst[i] = __floats2half2_rn(xf[2 * i], xf[2 * i + 1]);
    }

    int warp = threadIdx.x >> 5;
    int lane = threadIdx.x & 31;

    for (int sub = 0; sub < 4; sub++) {
        int e = warp + sub * 8;
        const float* w = gate_w + (size_t)e * H_DIM;
        float p0 = 0.f, p1 = 0.f, p2 = 0.f, p3 = 0.f;
        for (int h = lane; h < H_DIM; h += 32) {
            float wv = w[h];
            p0 += xs[0][h] * wv;
            p1 += xs[1][h] * wv;
            p2 += xs[2][h] * wv;
            p3 += xs[3][h] * wv;
        }
        for (int o = 16; o; o >>= 1) {
            p0 += __shfl_xor_sync(0xFFFFFFFFu, p0, o);
            p1 += __shfl_xor_sync(0xFFFFFFFFu, p1, o);
            p2 += __shfl_xor_sync(0xFFFFFFFFu, p2, o);
            p3 += __shfl_xor_sync(0xFFFFFFFFu, p3, o);
        }
        if (lane == 0) { lg[0][e] = p0; lg[1][e] = p1; lg[2][e] = p2; lg[3][e] = p3; }
    }
    __syncthreads();

    if (warp < TPB) {
        int t = t0 + warp;
        float logit = lg[warp][lane];
        if (logits_out) logits_out[(size_t)t * E_NUM + lane] = logit;

        float m = logit;
        for (int o = 16; o; o >>= 1) m = fmaxf(m, __shfl_xor_sync(0xFFFFFFFFu, m, o));
        float ex = expf(logit - m);
        float s = ex;
        for (int o = 16; o; o >>= 1) s += __shfl_xor_sync(0xFFFFFFFFu, s, o);
        float prob = ex / s;

        float v = prob;
        float wsum = 0.f;
        float selw[K_TOP];
        int   sele[K_TOP];
#pragma unroll
        for (int k = 0; k < K_TOP; k++) {
            float mv = v;
            for (int o = 16; o; o >>= 1) mv = fmaxf(mv, __shfl_xor_sync(0xFFFFFFFFu, mv, o));
            unsigned msk = __ballot_sync(0xFFFFFFFFu, v == mv);
            int src = __ffs(msk) - 1;
            if (lane == 0) { sele[k] = src; selw[k] = mv; wsum += mv; }
            if (lane == src) v = -1.f;
        }
        if (lane == 0) {
#pragma unroll
            for (int k = 0; k < K_TOP; k++) {
                int e = sele[k];
                float wn = selw[k] / wsum;
                int pos = atomicAdd(&g_cnt[e], 1);
                g_list_tok[e * T_TOK + pos] = t;
                g_list_w[e * T_TOK + pos]   = wn;
                g_list_tk[e * T_TOK + pos]  = t * K_TOP + k;
            }
        }
    }
}

__global__ void scan_remap_kernel() {
    if (threadIdx.x == 0) {
        int acc = 0;
        for (int e = 0; e < E_NUM; e++) { g_off[e] = acc; acc += g_cnt[e]; }
        g_off[E_NUM] = acc;
    }
    __syncthreads();
    for (int e = 0; e < E_NUM; e++) {
        int n = g_cnt[e], o = g_off[e];
        for (int p = threadIdx.x; p < n; p += blockDim.x)
            g_slot_of[g_list_tk[e * T_TOK + p]] = o + p;
    }
}

__device__ __forceinline__ float silu_f(float g) { return g / (1.f + expf(-g)); }

__device__ __forceinline__ uint32_t smem_u32(const void* p) {
    uint32_t a;
    asm("{ .reg .u64 t; cvta.to.shared.u64 t, %1; cvt.u32.u64 %0, t; }" : "=r"(a) : "l"(p));
    return a;
}

#define LDM4(r0, r1, r2, r3, addr) \
    asm volatile("ldmatrix.sync.aligned.m8n8.x4.shared.b16 {%0,%1,%2,%3}, [%4];" \
                 : "=r"(r0), "=r"(r1), "=r"(r2), "=r"(r3) : "r"(addr))

#define CP16(dst, src) \
    asm volatile("cp.async.cg.shared.global [%0], [%1], 16;" :: "r"(dst), "l"(src) : "memory")
#define CP_COMMIT() asm volatile("cp.async.commit_group;" ::: "memory")
#define CP_WAIT(n)  asm volatile("cp.async.wait_group %0;" :: "n"(n) : "memory")

__device__ __forceinline__ void mma16(float* c, uint32_t a0, uint32_t a1, uint32_t a2, uint32_t a3,
                                      uint32_t b0, uint32_t b1) {
    asm volatile("mma.sync.aligned.m16n8k16.row.col.f32.f16.f16.f32 "
                 "{%0,%1,%2,%3}, {%4,%5,%6,%7}, {%8,%9}, {%0,%1,%2,%3};"
                 : "+f"(c[0]), "+f"(c[1]), "+f"(c[2]), "+f"(c[3])
                 : "r"(a0), "r"(a1), "r"(a2), "r"(a3), "r"(b0), "r"(b1));
}

extern __shared__ unsigned char dsm[];

// ---------------- spin wait helper ----------------
__device__ __forceinline__ void wait_counter(int* ctr, int target) {
    if (threadIdx.x == 0) {
        while (atomicAdd(ctr, 0) < target) __nanosleep(128);
        __threadfence();
    }
    __syncthreads();
}

// ---------------- convert item: 98304 floats fp32 -> fp16 ----------------
__device__ void do_convert(const float* __restrict__ src, __half* __restrict__ dst,
                           int* ctr) {
    int tid = threadIdx.x;
    const float4* s4 = (const float4*)src;
#pragma unroll 4
    for (int i = tid; i < CV_CHUNK / 4; i += 256) {
        float4 v = s4[i];
        __half2 h[2];
        h[0] = __floats2half2_rn(v.x, v.y);
        h[1] = __floats2half2_rn(v.z, v.w);
        *(uint2*)(dst + i * 4) = *(uint2*)h;
    }
    __syncthreads();
    if (tid == 0) { __threadfence(); atomicAdd(ctr, 1); }
}

// ---------------- gateup tile ----------------
__device__ void do_gateup(int e, int m0, int c0) {
    int n = g_cnt[e];
    int tid = threadIdx.x;
    if (m0 >= n) {
        __syncthreads();
        if (tid == 0) atomicAdd(&g_done[e], 1);
        return;
    }
    wait_counter(&g_cvg[e], 32);

    uint32_t sbase = smem_u32(dsm);
    int lane = tid & 31;
    int warp = tid >> 5;
    int wM = warp & 3;
    int wN = warp >> 2;

    int lr = tid >> 1;
    int hf = tid & 1;
    int tokA = g_list_tok[e * T_TOK + min(m0 + lr, n - 1)];
    const __half* pA = g_xh + (size_t)tokA * H_DIM + hf * 16;
    uint32_t soA = lr * RSB + hf * 32;

    // B loader (fp16): 2 thr/row over 128 rows, 32B piece each
    int brow = tid >> 1;
    int bpc  = tid & 1;
    const __half* pB = (brow < 64)
        ? g_gw16 + ((size_t)e * I_DIM + (c0 + brow)) * H_DIM
        : g_uw16 + ((size_t)e * I_DIM + (c0 + brow - 64)) * H_DIM;
    pB += bpc * 16;
    uint32_t soBd = brow * RSB + bpc * 32;

    int mat = lane >> 3, rr = lane & 7;
    uint32_t aBase[2], bgBase[2], buBase[2];
#pragma unroll
    for (int mi = 0; mi < 2; mi++)
        aBase[mi] = sbase + (uint32_t)((wM * 32 + mi * 16 + (mat & 1) * 8 + rr) * RSB + (mat >> 1) * 16);
#pragma unroll
    for (int p = 0; p < 2; p++) {
        uint32_t roff = (uint32_t)((wN * 32 + p * 16 + (mat >> 1) * 8 + rr) * RSB + (mat & 1) * 16);
        bgBase[p] = sbase + roff;
        buBase[p] = sbase + 64 * RSB + roff;
    }

    float cg[2][4][4] = {};
    float cu[2][4][4] = {};

#define GU_A_PAIR(pr)                                                         \
    { int s0_ = 2 * (pr), s1_ = s0_ + 1;                                      \
      uint32_t b0_ = (uint32_t)(s0_ % ASTAGES) * A_STG;                       \
      uint32_t b1_ = (uint32_t)(s1_ % ASTAGES) * A_STG;                       \
      const __half* a0_ = pA + s0_ * 32;                                      \
      const __half* a1_ = pA + s1_ * 32;                                      \
      CP16(sbase + b0_ + soA, a0_); CP16(sbase + b0_ + soA + 16, a0_ + 8);    \
      CP16(sbase + b1_ + soA, a1_); CP16(sbase + b1_ + soA + 16, a1_ + 8); }

#define GU_COMP(astOff, bOff)                                                 \
    { _Pragma("unroll")                                                       \
      for (int ks = 0; ks < 2; ks++) {                                        \
        uint32_t af[2][4];                                                    \
        _Pragma("unroll")                                                     \
        for (int mi = 0; mi < 2; mi++)                                        \
            LDM4(af[mi][0], af[mi][1], af[mi][2], af[mi][3], aBase[mi] + (astOff) + ks * 32); \
        uint32_t gf[2][4], uf[2][4];                                          \
        _Pragma("unroll")                                                     \
        for (int p = 0; p < 2; p++) {                                         \
            LDM4(gf[p][0], gf[p][1], gf[p][2], gf[p][3], bgBase[p] + (bOff) + ks * 32); \
            LDM4(uf[p][0], uf[p][1], uf[p][2], uf[p][3], buBase[p] + (bOff) + ks * 32); \
        }                                                                     \
        _Pragma("unroll")                                                     \
        for (int t = 0; t < 4; t++) {                                         \
            int p = t >> 1, q = (t & 1) * 2;                                  \
            _Pragma("unroll")                                                 \
            for (int mi = 0; mi < 2; mi++) {                                  \
                mma16(cg[mi][t], af[mi][0], af[mi][1], af[mi][2], af[mi][3], gf[p][q], gf[p][q + 1]); \
                mma16(cu[mi][t], af[mi][0], af[mi][1], af[mi][2], af[mi][3], uf[p][q], uf[p][q + 1]); \
            }                                                                 \
        }                                                                     \
      } }

    GU_A_PAIR(0); CP_COMMIT();
    GU_A_PAIR(1); CP_COMMIT();
    {
        uint4 v0 = *(const uint4*)(pB);
        uint4 v1 = *(const uint4*)(pB + 8);
        *(uint4*)(dsm + GU_DEST + soBd)      = v0;
        *(uint4*)(dsm + GU_DEST + soBd + 16) = v1;
        v0 = *(const uint4*)(pB + 32);
        v1 = *(const uint4*)(pB + 40);
        *(uint4*)(dsm + GU_DEST + GU_SLABB + soBd)      = v0;
        *(uint4*)(dsm + GU_DEST + GU_SLABB + soBd + 16) = v1;
    }

    for (int j = 0; j < GU_NP; j++) {
        CP_WAIT(1);
        __syncthreads();
        uint32_t pbr = GU_DEST + (uint32_t)(j & 1) * GU_PBUF;
        uint32_t pbw = GU_DEST + (uint32_t)((j + 1) & 1) * GU_PBUF;
        int s0 = 2 * j;
        int sn0 = s0 + 2, sn1 = s0 + 3;
        bool hn = (j + 1 < GU_NP);

        uint4 v0, v1;
        if (hn) {
            v0 = *(const uint4*)(pB + sn0 * 32);
            v1 = *(const uint4*)(pB + sn0 * 32 + 8);
        }

        GU_COMP((uint32_t)(s0 % ASTAGES) * A_STG, pbr);

        if (hn) {
            *(uint4*)(dsm + pbw + soBd)      = v0;
            *(uint4*)(dsm + pbw + soBd + 16) = v1;
            v0 = *(const uint4*)(pB + sn1 * 32);
            v1 = *(const uint4*)(pB + sn1 * 32 + 8);
        }

        GU_COMP((uint32_t)((s0 + 1) % ASTAGES) * A_STG, pbr + GU_SLABB);

        if (hn) {
            *(uint4*)(dsm + pbw + GU_SLABB + soBd)      = v0;
            *(uint4*)(dsm + pbw + GU_SLABB + soBd + 16) = v1;
        }
        if (j + 2 < GU_NP) GU_A_PAIR(j + 2);
        CP_COMMIT();
    }
#undef GU_A_PAIR
#undef GU_COMP

    int off = g_off[e];
    int g  = lane >> 2;
    int tq = lane & 3;
#pragma unroll
    for (int mi = 0; mi < 2; mi++) {
        int r0 = m0 + wM * 32 + mi * 16 + g;
        int r1 = r0 + 8;
        float w0 = (r0 < n) ? g_list_w[e * T_TOK + r0] : 0.f;
        float w1 = (r1 < n) ? g_list_w[e * T_TOK + r1] : 0.f;
#pragma unroll
        for (int t = 0; t < 4; t++) {
            int col = c0 + wN * 32 + t * 8 + 2 * tq;
            if (r0 < n) {
                float ox = silu_f(cg[mi][t][0]) * cu[mi][t][0] * w0;
                float oy = silu_f(cg[mi][t][1]) * cu[mi][t][1] * w0;
                *(__half2*)&g_act[((size_t)(off + r0)) * I_DIM + col] = __floats2half2_rn(ox, oy);
            }
            if (r1 < n) {
                float ox = silu_f(cg[mi][t][2]) * cu[mi][t][2] * w1;
                float oy = silu_f(cg[mi][t][3]) * cu[mi][t][3] * w1;
                *(__half2*)&g_act[((size_t)(off + r1)) * I_DIM + col] = __floats2half2_rn(ox, oy);
            }
        }
    }

    __syncthreads();
    if (tid == 0) { __threadfence(); atomicAdd(&g_done[e], 1); }
}

// ---------------- down tile (BN=128) ----------------
__device__ void do_down(int e, int m0, int c0) {
    int n = g_cnt[e];
    int tid = threadIdx.x;
    if (m0 >= n) {
        __syncthreads();
        if (tid == 0) atomicAdd(&g_dn_all, 1);
        return;
    }
    wait_counter(&g_cvd[e], 16);
    wait_counter(&g_done[e], GU_PER_E);

    int off = g_off[e];
    uint32_t sbase = smem_u32(dsm);
    int lane = tid & 31;
    int warp = tid >> 5;
    int wM = warp & 3;
    int wN = warp >> 2;

    int lr = tid >> 1;
    int hf = tid & 1;
    const __half* pA = g_act + (size_t)(off + min(m0 + lr, n - 1)) * I_DIM + hf * 16;
    uint32_t soA = lr * RSB + hf * 32;

    int brow = tid >> 1;
    int bpc  = tid & 1;
    const __half* pB = g_dw16 + ((size_t)e * H_DIM + (c0 + brow)) * I_DIM + bpc * 16;
    uint32_t soBd = brow * RSB + bpc * 32;

    int mat = lane >> 3, rr = lane & 7;
    uint32_t aBase[2], bBase[4];
#pragma unroll
    for (int mi = 0; mi < 2; mi++)
        aBase[mi] = sbase + (uint32_t)((wM * 32 + mi * 16 + (mat & 1) * 8 + rr) * RSB + (mat >> 1) * 16);
#pragma unroll
    for (int p = 0; p < 4; p++)
        bBase[p] = sbase + (uint32_t)((wN * 64 + p * 16 + (mat >> 1) * 8 + rr) * RSB + (mat & 1) * 16);

    float c[2][8][4] = {};

#define DN_A_PAIR(pr)                                                         \
    { int s0_ = 2 * (pr), s1_ = s0_ + 1;                                      \
      uint32_t b0_ = (uint32_t)(s0_ % ASTAGES) * A_STG;                       \
      uint32_t b1_ = (uint32_t)(s1_ % ASTAGES) * A_STG;                       \
      const __half* a0_ = pA + s0_ * 32;                                      \
      const __half* a1_ = pA + s1_ * 32;                                      \
      CP16(sbase + b0_ + soA, a0_); CP16(sbase + b0_ + soA + 16, a0_ + 8);    \
      CP16(sbase + b1_ + soA, a1_); CP16(sbase + b1_ + soA + 16, a1_ + 8); }

#define DN_COMP(astOff, bOff)                                                 \
    { _Pragma("unroll")                                                       \
      for (int ks = 0; ks < 2; ks++) {                                        \
        uint32_t af[2][4];                                                    \
        _Pragma("unroll")                                                     \
        for (int mi = 0; mi < 2; mi++)                                        \
            LDM4(af[mi][0], af[mi][1], af[mi][2], af[mi][3], aBase[mi] + (astOff) + ks * 32); \
        uint32_t bf[4][4];                                                    \
        _Pragma("unroll")                                                     \
        for (int p = 0; p < 4; p++)                                           \
            LDM4(bf[p][0], bf[p][1], bf[p][2], bf[p][3], bBase[p] + (bOff) + ks * 32); \
        _Pragma("unroll")                                                     \
        for (int t = 0; t < 8; t++) {                                         \
            int p = t >> 1, q = (t & 1) * 2;                                  \
            _Pragma("unroll")                                                 \
            for (int mi = 0; mi < 2; mi++)                                    \
                mma16(c[mi][t], af[mi][0], af[mi][1], af[mi][2], af[mi][3], bf[p][q], bf[p][q + 1]); \
        }                                                                     \
      } }

    DN_A_PAIR(0); CP_COMMIT();
    DN_A_PAIR(1); CP_COMMIT();
    {
        uint4 v0 = *(const uint4*)(pB);
        uint4 v1 = *(const uint4*)(pB + 8);
        *(uint4*)(dsm + DN_DEST + soBd)      = v0;
        *(uint4*)(dsm + DN_DEST + soBd + 16) = v1;
        v0 = *(const uint4*)(pB + 32);
        v1 = *(const uint4*)(pB + 40);
        *(uint4*)(dsm + DN_DEST + DN_SLABB + soBd)      = v0;
        *(uint4*)(dsm + DN_DEST + DN_SLABB + soBd + 16) = v1;
    }

    for (int j = 0; j < DN_NP; j++) {
        CP_WAIT(1);
        __syncthreads();
        uint32_t pbr = DN_DEST + (uint32_t)(j & 1) * DN_PBUF;
        uint32_t pbw = DN_DEST + (uint32_t)((j + 1) & 1) * DN_PBUF;
        int s0 = 2 * j;
        int sn0 = s0 + 2, sn1 = s0 + 3;
        bool hn = (j + 1 < DN_NP);

        uint4 v0, v1;
        if (hn) {
            v0 = *(const uint4*)(pB + sn0 * 32);
            v1 = *(const uint4*)(pB + sn0 * 32 + 8);
        }

        DN_COMP((uint32_t)(s0 % ASTAGES) * A_STG, pbr);

        if (hn) {
            *(uint4*)(dsm + pbw + soBd)      = v0;
            *(uint4*)(dsm + pbw + soBd + 16) = v1;
            v0 = *(const uint4*)(pB + sn1 * 32);
            v1 = *(const uint4*)(pB + sn1 * 32 + 8);
        }

        DN_COMP((uint32_t)((s0 + 1) % ASTAGES) * A_STG, pbr + DN_SLABB);

        if (hn) {
            *(uint4*)(dsm + pbw + DN_SLABB + soBd)      = v0;
            *(uint4*)(dsm + pbw + DN_SLABB + soBd + 16) = v1;
        }
        if (j + 2 < DN_NP) DN_A_PAIR(j + 2);
        CP_COMMIT();
    }
#undef DN_A_PAIR
#undef DN_COMP

    int g  = lane >> 2;
    int tq = lane & 3;
#pragma unroll
    for (int mi = 0; mi < 2; mi++) {
        int r0 = m0 + wM * 32 + mi * 16 + g;
        int r1 = r0 + 8;
#pragma unroll
        for (int t = 0; t < 8; t++) {
            int col = c0 + wN * 64 + t * 8 + 2 * tq;
            if (r0 < n)
                *(__half2*)&g_pair[((size_t)(off + r0)) * H_DIM + col] =
                    __floats2half2_rn(c[mi][t][0], c[mi][t][1]);
            if (r1 < n)
                *(__half2*)&g_pair[((size_t)(off + r1)) * H_DIM + col] =
                    __floats2half2_rn(c[mi][t][2], c[mi][t][3]);
        }
    }

    __syncthreads();
    if (tid == 0) { __threadfence(); atomicAdd(&g_dn_all, 1); }
}

// ---------------- reduce item: one token ----------------
__device__ void do_reduce(int t, float* __restrict__ out) {
    wait_counter(&g_dn_all, DN_ITEMS);
    int s[K_TOP];
#pragma unroll
    for (int k = 0; k < K_TOP; k++) s[k] = g_slot_of[t * K_TOP + k];
    int i = threadIdx.x;
    float acc[8] = {};
#pragma unroll
    for (int k = 0; k < K_TOP; k++) {
        uint4 v = *(const uint4*)&g_pair[(size_t)s[k] * H_DIM + i * 8];
        const __half2* h = (const __half2*)&v;
#pragma unroll
        for (int q = 0; q < 4; q++) {
            float2 f = __half22float2(h[q]);
            acc[2 * q]     += f.x;
            acc[2 * q + 1] += f.y;
        }
    }
    float4* ob = (float4*)(out + (size_t)t * H_DIM + i * 8);
    ob[0] = make_float4(acc[0], acc[1], acc[2], acc[3]);
    ob[1] = make_float4(acc[4], acc[5], acc[6], acc[7]);
}

// ---------------- persistent fused MoE kernel ----------------
__global__ __launch_bounds__(256, 2) void moe_kernel(const float* __restrict__ gw,
                                                     const float* __restrict__ uw,
                                                     const float* __restrict__ dw,
                                                     float* __restrict__ out) {
    __shared__ int s_item;
    for (;;) {
        if (threadIdx.x == 0) s_item = atomicAdd(&g_work, 1);
        __syncthreads();
        int item = s_item;
        __syncthreads();
        if (item >= TOT_ITEMS) return;

        if (item < CV_ITEMS) {
            int e   = item / CV_PER_E;
            int sub = item % CV_PER_E;
            if (sub < 16) {
                size_t o = (size_t)e * W_PER_E + (size_t)sub * CV_CHUNK;
                do_convert(gw + o, g_gw16 + o, &g_cvg[e]);
            } else if (sub < 32) {
                size_t o = (size_t)e * W_PER_E + (size_t)(sub - 16) * CV_CHUNK;
                do_convert(uw + o, g_uw16 + o, &g_cvg[e]);
            } else {
                size_t o = (size_t)e * W_PER_E + (size_t)(sub - 32) * CV_CHUNK;
                do_convert(dw + o, g_dw16 + o, &g_cvd[e]);
            }
        } else if (item < DN_BASE) {
            int it = item - GU_BASE;
            int e = it / GU_PER_E;
            int r = it % GU_PER_E;
            do_gateup(e, (r & (GU_XT - 1)) * BM, (r >> 3) * BN);
        } else if (item < RD_BASE) {
            int it = item - DN_BASE;
            int e = it / DN_PER_E;
            int r = it % DN_PER_E;
            do_down(e, (r & (GU_XT - 1)) * BM, (r >> 3) * DN_BN);
        } else {
            do_reduce(item - RD_BASE, out);
        }
    }
}

// ---------------- launch ----------------
extern "C" void kernel_launch(void* const* d_in, const int* in_sizes, int n_in,
                              void* d_out, int out_size) {
    const float* x      = (const float*)d_in[0];
    const float* gate_w = (const float*)d_in[1];
    const float* gw     = (const float*)d_in[2];
    const float* uw     = (const float*)d_in[3];
    const float* dw     = (const float*)d_in[4];
    float* out = (float*)d_out;

    float* logits = (out_size >= T_TOK * H_DIM + T_TOK * E_NUM) ? (out + (size_t)T_TOK * H_DIM)
                                                                : (float*)0;

    cudaFuncSetAttribute(moe_kernel, cudaFuncAttributeMaxDynamicSharedMemorySize, MOE_SMEM);

    zero_cnt_kernel<<<1, 32>>>();
    router_kernel<<<T_TOK / 4, 256>>>(x, gate_w, logits);
    scan_remap_kernel<<<1, 256>>>();
    moe_kernel<<<304, 256, MOE_SMEM>>>(gw, uw, dw, out);
}

// round 17
// speedup vs baseline: 1.2575x; 1.2575x over previous
#include <cuda_runtime.h>
#include <cuda_fp16.h>
#include <math.h>
#include <stdint.h>

#define T_TOK 1024
#define H_DIM 2048
#define I_DIM 768
#define E_NUM 32
#define K_TOP 8

#define BM 128
#define BN 64            // gateup N tile (x2 for gate+up)
#define DN_BN 128        // down N tile
#define BK 32
#define RSB 80
#define ASTAGES 6

#define A_STG    (BM * RSB)                 // 10240
#define GU_SLABB (2 * BN * RSB)             // 10240
#define GU_PBUF  (2 * GU_SLABB)             // 20480
#define GU_DEST  (ASTAGES * A_STG)          // 61440
#define DN_SLABB (DN_BN * RSB)
#define DN_PBUF  (2 * DN_SLABB)
#define DN_DEST  (ASTAGES * A_STG)
#define MOE_SMEM 102400

#define GU_NC (H_DIM / BK)
#define GU_NP (GU_NC / 2)                   // 32
#define DN_NC (I_DIM / BK)
#define DN_NP (DN_NC / 2)                   // 12

#define GU_XT (T_TOK / BM)                  // 8
#define GU_YT (I_DIM / BN)                  // 12
#define DN_YT (H_DIM / DN_BN)               // 16
#define GU_PER_E (GU_XT * GU_YT)            // 96
#define DN_PER_E (GU_XT * DN_YT)            // 128
#define GU_ITEMS (GU_PER_E * E_NUM)         // 3072
#define DN_ITEMS (DN_PER_E * E_NUM)         // 4096
#define RD_ITEMS T_TOK                      // 1024
#define DN_BASE  GU_ITEMS
#define RD_BASE  (DN_BASE + DN_ITEMS)       // 7168
#define TOT_ITEMS (RD_BASE + RD_ITEMS)      // 8192

// ---------------- scratch ----------------
__device__ int    g_cnt[E_NUM];
__device__ int    g_off[E_NUM + 1];
__device__ int    g_list_tok[E_NUM * T_TOK];
__device__ float  g_list_w[E_NUM * T_TOK];
__device__ int    g_list_tk[E_NUM * T_TOK];
__device__ int    g_slot_of[T_TOK * K_TOP];
__device__ __half g_act[(size_t)T_TOK * K_TOP * I_DIM];
__device__ __half g_pair[(size_t)T_TOK * K_TOP * H_DIM];
__device__ __half g_xh[(size_t)T_TOK * H_DIM];
__device__ int    g_work;
__device__ int    g_done[E_NUM];
__device__ int    g_dn_all;

__global__ void zero_cnt_kernel() {
    if (threadIdx.x < E_NUM) { g_cnt[threadIdx.x] = 0; g_done[threadIdx.x] = 0; }
    if (threadIdx.x == 0) { g_work = 0; g_dn_all = 0; }
}

// ---------------- router (+ fp16 copy of x) ----------------
__global__ void router_kernel(const float* __restrict__ x,
                              const float* __restrict__ gate_w,
                              float* __restrict__ logits_out) {
    const int TPB = 4;
    __shared__ float xs[TPB][H_DIM];
    __shared__ float lg[TPB][E_NUM];

    int t0 = blockIdx.x * TPB;
    const float4* xv  = (const float4*)(x + (size_t)t0 * H_DIM);
    float4*       xsv = (float4*)&xs[0][0];
    for (int i = threadIdx.x; i < TPB * H_DIM / 4; i += blockDim.x) xsv[i] = xv[i];
    __syncthreads();

    {
        const float* xf = &xs[0][0];
        __half2* dst = (__half2*)(g_xh + (size_t)t0 * H_DIM);
        for (int i = threadIdx.x; i < TPB * H_DIM / 2; i += blockDim.x)
            dst[i] = __floats2half2_rn(xf[2 * i], xf[2 * i + 1]);
    }

    int warp = threadIdx.x >> 5;
    int lane = threadIdx.x & 31;

    for (int sub = 0; sub < 4; sub++) {
        int e = warp + sub * 8;
        const float* w = gate_w + (size_t)e * H_DIM;
        float p0 = 0.f, p1 = 0.f, p2 = 0.f, p3 = 0.f;
        for (int h = lane; h < H_DIM; h += 32) {
            float wv = w[h];
            p0 += xs[0][h] * wv;
            p1 += xs[1][h] * wv;
            p2 += xs[2][h] * wv;
            p3 += xs[3][h] * wv;
        }
        for (int o = 16; o; o >>= 1) {
            p0 += __shfl_xor_sync(0xFFFFFFFFu, p0, o);
            p1 += __shfl_xor_sync(0xFFFFFFFFu, p1, o);
            p2 += __shfl_xor_sync(0xFFFFFFFFu, p2, o);
            p3 += __shfl_xor_sync(0xFFFFFFFFu, p3, o);
        }
        if (lane == 0) { lg[0][e] = p0; lg[1][e] = p1; lg[2][e] = p2; lg[3][e] = p3; }
    }
    __syncthreads();

    if (warp < TPB) {
        int t = t0 + warp;
        float logit = lg[warp][lane];
        if (logits_out) logits_out[(size_t)t * E_NUM + lane] = logit;

        float m = logit;
        for (int o = 16; o; o >>= 1) m = fmaxf(m, __shfl_xor_sync(0xFFFFFFFFu, m, o));
        float ex = expf(logit - m);
        float s = ex;
        for (int o = 16; o; o >>= 1) s += __shfl_xor_sync(0xFFFFFFFFu, s, o);
        float prob = ex / s;

        float v = prob;
        float wsum = 0.f;
        float selw[K_TOP];
        int   sele[K_TOP];
#pragma unroll
        for (int k = 0; k < K_TOP; k++) {
            float mv = v;
            for (int o = 16; o; o >>= 1) mv = fmaxf(mv, __shfl_xor_sync(0xFFFFFFFFu, mv, o));
            unsigned msk = __ballot_sync(0xFFFFFFFFu, v == mv);
            int src = __ffs(msk) - 1;
            if (lane == 0) { sele[k] = src; selw[k] = mv; wsum += mv; }
            if (lane == src) v = -1.f;
        }
        if (lane == 0) {
#pragma unroll
            for (int k = 0; k < K_TOP; k++) {
                int e = sele[k];
                float wn = selw[k] / wsum;
                int pos = atomicAdd(&g_cnt[e], 1);
                g_list_tok[e * T_TOK + pos] = t;
                g_list_w[e * T_TOK + pos]   = wn;
                g_list_tk[e * T_TOK + pos]  = t * K_TOP + k;
            }
        }
    }
}

// ---------------- fused scan + remap ----------------
__global__ void scan_remap_kernel() {
    if (threadIdx.x == 0) {
        int acc = 0;
        for (int e = 0; e < E_NUM; e++) { g_off[e] = acc; acc += g_cnt[e]; }
        g_off[E_NUM] = acc;
    }
    __syncthreads();
    for (int e = 0; e < E_NUM; e++) {
        int n = g_cnt[e], o = g_off[e];
        for (int p = threadIdx.x; p < n; p += blockDim.x)
            g_slot_of[g_list_tk[e * T_TOK + p]] = o + p;
    }
}

__device__ __forceinline__ float silu_f(float g) { return g / (1.f + expf(-g)); }

__device__ __forceinline__ uint32_t smem_u32(const void* p) {
    uint32_t a;
    asm("{ .reg .u64 t; cvta.to.shared.u64 t, %1; cvt.u32.u64 %0, t; }" : "=r"(a) : "l"(p));
    return a;
}

#define LDM4(r0, r1, r2, r3, addr) \
    asm volatile("ldmatrix.sync.aligned.m8n8.x4.shared.b16 {%0,%1,%2,%3}, [%4];" \
                 : "=r"(r0), "=r"(r1), "=r"(r2), "=r"(r3) : "r"(addr))

#define CP16(dst, src) \
    asm volatile("cp.async.cg.shared.global [%0], [%1], 16;" :: "r"(dst), "l"(src) : "memory")
#define CP_COMMIT() asm volatile("cp.async.commit_group;" ::: "memory")
#define CP_WAIT(n)  asm volatile("cp.async.wait_group %0;" :: "n"(n) : "memory")

__device__ __forceinline__ void mma16(float* c, uint32_t a0, uint32_t a1, uint32_t a2, uint32_t a3,
                                      uint32_t b0, uint32_t b1) {
    asm volatile("mma.sync.aligned.m16n8k16.row.col.f32.f16.f16.f32 "
                 "{%0,%1,%2,%3}, {%4,%5,%6,%7}, {%8,%9}, {%0,%1,%2,%3};"
                 : "+f"(c[0]), "+f"(c[1]), "+f"(c[2]), "+f"(c[3])
                 : "r"(a0), "r"(a1), "r"(a2), "r"(a3), "r"(b0), "r"(b1));
}

__device__ __forceinline__ void cvt_sts(unsigned char* dst, float4 v0, float4 v1) {
    __half2 h[4];
    h[0] = __floats2half2_rn(v0.x, v0.y);
    h[1] = __floats2half2_rn(v0.z, v0.w);
    h[2] = __floats2half2_rn(v1.x, v1.y);
    h[3] = __floats2half2_rn(v1.z, v1.w);
    *(uint4*)dst = *(uint4*)h;
}

extern __shared__ unsigned char dsm[];

// ---------------- spin wait helper ----------------
__device__ __forceinline__ void wait_counter(int* ctr, int target) {
    if (threadIdx.x == 0) {
        while (atomicAdd(ctr, 0) < target) __nanosleep(128);
        __threadfence();
    }
    __syncthreads();
}

// ---------------- gateup tile ----------------
__device__ void do_gateup(int e, int m0, int c0,
                          const float* __restrict__ gw, const float* __restrict__ uw) {
    int n = g_cnt[e];
    int tid = threadIdx.x;
    if (m0 >= n) {
        __syncthreads();
        if (tid == 0) atomicAdd(&g_done[e], 1);
        return;
    }

    uint32_t sbase = smem_u32(dsm);
    int lane = tid & 31;
    int warp = tid >> 5;
    int wM = warp & 3;
    int wN = warp >> 2;

    int lr = tid >> 1;
    int hf = tid & 1;
    int tokA = g_list_tok[e * T_TOK + min(m0 + lr, n - 1)];
    const __half* pA = g_xh + (size_t)tokA * H_DIM + hf * 16;
    uint32_t soA = lr * RSB + hf * 32;

    const float* pB[2];
    uint32_t soBd[2];
#pragma unroll
    for (int j = 0; j < 2; j++) {
        int c = tid + 256 * j;
        int row = c >> 2;
        const float* base = (row < 64)
            ? gw + ((size_t)e * I_DIM + (c0 + row)) * H_DIM
            : uw + ((size_t)e * I_DIM + (c0 + row - 64)) * H_DIM;
        pB[j]   = base + (c & 3) * 8;
        soBd[j] = row * RSB + (c & 3) * 16;
    }

    int mat = lane >> 3, rr = lane & 7;
    uint32_t aBase[2], bgBase[2], buBase[2];
#pragma unroll
    for (int mi = 0; mi < 2; mi++)
        aBase[mi] = sbase + (uint32_t)((wM * 32 + mi * 16 + (mat & 1) * 8 + rr) * RSB + (mat >> 1) * 16);
#pragma unroll
    for (int p = 0; p < 2; p++) {
        uint32_t roff = (uint32_t)((wN * 32 + p * 16 + (mat >> 1) * 8 + rr) * RSB + (mat & 1) * 16);
        bgBase[p] = sbase + roff;
        buBase[p] = sbase + 64 * RSB + roff;
    }

    float cg[2][4][4] = {};
    float cu[2][4][4] = {};

#define GU_A_PAIR(pr)                                                         \
    { int s0_ = 2 * (pr), s1_ = s0_ + 1;                                      \
      uint32_t b0_ = (uint32_t)(s0_ % ASTAGES) * A_STG;                       \
      uint32_t b1_ = (uint32_t)(s1_ % ASTAGES) * A_STG;                       \
      const __half* a0_ = pA + s0_ * 32;                                      \
      const __half* a1_ = pA + s1_ * 32;                                      \
      CP16(sbase + b0_ + soA, a0_); CP16(sbase + b0_ + soA + 16, a0_ + 8);    \
      CP16(sbase + b1_ + soA, a1_); CP16(sbase + b1_ + soA + 16, a1_ + 8); }

#define GU_COMP(astOff, bOff)                                                 \
    { _Pragma("unroll")                                                       \
      for (int ks = 0; ks < 2; ks++) {                                        \
        uint32_t af[2][4];                                                    \
        _Pragma("unroll")                                                     \
        for (int mi = 0; mi < 2; mi++)                                        \
            LDM4(af[mi][0], af[mi][1], af[mi][2], af[mi][3], aBase[mi] + (astOff) + ks * 32); \
        uint32_t gf[2][4], uf[2][4];                                          \
        _Pragma("unroll")                                                     \
        for (int p = 0; p < 2; p++) {                                         \
            LDM4(gf[p][0], gf[p][1], gf[p][2], gf[p][3], bgBase[p] + (bOff) + ks * 32); \
            LDM4(uf[p][0], uf[p][1], uf[p][2], uf[p][3], buBase[p] + (bOff) + ks * 32); \
        }                                                                     \
        _Pragma("unroll")                                                     \
        for (int t = 0; t < 4; t++) {                                         \
            int p = t >> 1, q = (t & 1) * 2;                                  \
            _Pragma("unroll")                                                 \
            for (int mi = 0; mi < 2; mi++) {                                  \
                mma16(cg[mi][t], af[mi][0], af[mi][1], af[mi][2], af[mi][3], gf[p][q], gf[p][q + 1]); \
                mma16(cu[mi][t], af[mi][0], af[mi][1], af[mi][2], af[mi][3], uf[p][q], uf[p][q + 1]); \
            }                                                                 \
        }                                                                     \
      } }

    GU_A_PAIR(0); CP_COMMIT();
    GU_A_PAIR(1); CP_COMMIT();
    {
        float4 a0 = *(const float4*)(pB[0]);
        float4 a1 = *(const float4*)(pB[0] + 4);
        float4 b0 = *(const float4*)(pB[1]);
        float4 b1 = *(const float4*)(pB[1] + 4);
        cvt_sts(dsm + GU_DEST + soBd[0], a0, a1);
        cvt_sts(dsm + GU_DEST + soBd[1], b0, b1);
        const float* q0 = pB[0] + 32;
        const float* q1 = pB[1] + 32;
        a0 = *(const float4*)(q0); a1 = *(const float4*)(q0 + 4);
        b0 = *(const float4*)(q1); b1 = *(const float4*)(q1 + 4);
        cvt_sts(dsm + GU_DEST + GU_SLABB + soBd[0], a0, a1);
        cvt_sts(dsm + GU_DEST + GU_SLABB + soBd[1], b0, b1);
    }

    for (int j = 0; j < GU_NP; j++) {
        CP_WAIT(1);
        __syncthreads();
        uint32_t pbr = GU_DEST + (uint32_t)(j & 1) * GU_PBUF;
        uint32_t pbw = GU_DEST + (uint32_t)((j + 1) & 1) * GU_PBUF;
        int s0 = 2 * j;
        int sn0 = s0 + 2, sn1 = s0 + 3;
        bool hn = (j + 1 < GU_NP);

        float4 na, nb, nc, nd;
        if (hn) {
            const float* q0 = pB[0] + sn0 * 32;
            const float* q1 = pB[1] + sn0 * 32;
            na = *(const float4*)(q0); nb = *(const float4*)(q0 + 4);
            nc = *(const float4*)(q1); nd = *(const float4*)(q1 + 4);
        }

        GU_COMP((uint32_t)(s0 % ASTAGES) * A_STG, pbr);

        if (hn) {
            cvt_sts(dsm + pbw + soBd[0], na, nb);
            cvt_sts(dsm + pbw + soBd[1], nc, nd);
            const float* q0 = pB[0] + sn1 * 32;
            const float* q1 = pB[1] + sn1 * 32;
            na = *(const float4*)(q0); nb = *(const float4*)(q0 + 4);
            nc = *(const float4*)(q1); nd = *(const float4*)(q1 + 4);
        }

        GU_COMP((uint32_t)((s0 + 1) % ASTAGES) * A_STG, pbr + GU_SLABB);

        if (hn) {
            cvt_sts(dsm + pbw + GU_SLABB + soBd[0], na, nb);
            cvt_sts(dsm + pbw + GU_SLABB + soBd[1], nc, nd);
        }
        if (j + 2 < GU_NP) GU_A_PAIR(j + 2);
        CP_COMMIT();
    }
#undef GU_A_PAIR
#undef GU_COMP

    int off = g_off[e];
    int g  = lane >> 2;
    int tq = lane & 3;
#pragma unroll
    for (int mi = 0; mi < 2; mi++) {
        int r0 = m0 + wM * 32 + mi * 16 + g;
        int r1 = r0 + 8;
        float w0 = (r0 < n) ? g_list_w[e * T_TOK + r0] : 0.f;
        float w1 = (r1 < n) ? g_list_w[e * T_TOK + r1] : 0.f;
#pragma unroll
        for (int t = 0; t < 4; t++) {
            int col = c0 + wN * 32 + t * 8 + 2 * tq;
            if (r0 < n) {
                float ox = silu_f(cg[mi][t][0]) * cu[mi][t][0] * w0;
                float oy = silu_f(cg[mi][t][1]) * cu[mi][t][1] * w0;
                *(__half2*)&g_act[((size_t)(off + r0)) * I_DIM + col] = __floats2half2_rn(ox, oy);
            }
            if (r1 < n) {
                float ox = silu_f(cg[mi][t][2]) * cu[mi][t][2] * w1;
                float oy = silu_f(cg[mi][t][3]) * cu[mi][t][3] * w1;
                *(__half2*)&g_act[((size_t)(off + r1)) * I_DIM + col] = __floats2half2_rn(ox, oy);
            }
        }
    }

    __syncthreads();
    if (tid == 0) { __threadfence(); atomicAdd(&g_done[e], 1); }
}

// ---------------- down tile (BN=128) ----------------
__device__ void do_down(int e, int m0, int c0, const float* __restrict__ dw) {
    int n = g_cnt[e];
    int tid = threadIdx.x;
    if (m0 >= n) {
        __syncthreads();
        if (tid == 0) atomicAdd(&g_dn_all, 1);
        return;
    }

    wait_counter(&g_done[e], GU_PER_E);

    int off = g_off[e];
    uint32_t sbase = smem_u32(dsm);
    int lane = tid & 31;
    int warp = tid >> 5;
    int wM = warp & 3;
    int wN = warp >> 2;

    int lr = tid >> 1;
    int hf = tid & 1;
    const __half* pA = g_act + (size_t)(off + min(m0 + lr, n - 1)) * I_DIM + hf * 16;
    uint32_t soA = lr * RSB + hf * 32;

    const float* pB[2];
    uint32_t soBd[2];
#pragma unroll
    for (int j = 0; j < 2; j++) {
        int c = tid + 256 * j;
        int row = c >> 2;
        pB[j]   = dw + ((size_t)e * H_DIM + (c0 + row)) * I_DIM + (c & 3) * 8;
        soBd[j] = row * RSB + (c & 3) * 16;
    }

    int mat = lane >> 3, rr = lane & 7;
    uint32_t aBase[2], bBase[4];
#pragma unroll
    for (int mi = 0; mi < 2; mi++)
        aBase[mi] = sbase + (uint32_t)((wM * 32 + mi * 16 + (mat & 1) * 8 + rr) * RSB + (mat >> 1) * 16);
#pragma unroll
    for (int p = 0; p < 4; p++)
        bBase[p] = sbase + (uint32_t)((wN * 64 + p * 16 + (mat >> 1) * 8 + rr) * RSB + (mat & 1) * 16);

    float c[2][8][4] = {};

#define DN_A_PAIR(pr)                                                         \
    { int s0_ = 2 * (pr), s1_ = s0_ + 1;                                      \
      uint32_t b0_ = (uint32_t)(s0_ % ASTAGES) * A_STG;                       \
      uint32_t b1_ = (uint32_t)(s1_ % ASTAGES) * A_STG;                       \
      const __half* a0_ = pA + s0_ * 32;                                      \
      const __half* a1_ = pA + s1_ * 32;                                      \
      CP16(sbase + b0_ + soA, a0_); CP16(sbase + b0_ + soA + 16, a0_ + 8);    \
      CP16(sbase + b1_ + soA, a1_); CP16(sbase + b1_ + soA + 16, a1_ + 8); }

#define DN_COMP(astOff, bOff)                                                 \
    { _Pragma("unroll")                                                       \
      for (int ks = 0; ks < 2; ks++) {                                        \
        uint32_t af[2][4];                                                    \
        _Pragma("unroll")                                                     \
        for (int mi = 0; mi < 2; mi++)                                        \
            LDM4(af[mi][0], af[mi][1], af[mi][2], af[mi][3], aBase[mi] + (astOff) + ks * 32); \
        uint32_t bf[4][4];                                                    \
        _Pragma("unroll")                                                     \
        for (int p = 0; p < 4; p++)                                           \
            LDM4(bf[p][0], bf[p][1], bf[p][2], bf[p][3], bBase[p] + (bOff) + ks * 32); \
        _Pragma("unroll")                                                     \
        for (int t = 0; t < 8; t++) {                                         \
            int p = t >> 1, q = (t & 1) * 2;                                  \
            _Pragma("unroll")                                                 \
            for (int mi = 0; mi < 2; mi++)                                    \
                mma16(c[mi][t], af[mi][0], af[mi][1], af[mi][2], af[mi][3], bf[p][q], bf[p][q + 1]); \
        }                                                                     \
      } }

    DN_A_PAIR(0); CP_COMMIT();
    DN_A_PAIR(1); CP_COMMIT();
    {
        float4 a0 = *(const float4*)(pB[0]);
        float4 a1 = *(const float4*)(pB[0] + 4);
        float4 b0 = *(const float4*)(pB[1]);
        float4 b1 = *(const float4*)(pB[1] + 4);
        cvt_sts(dsm + DN_DEST + soBd[0], a0, a1);
        cvt_sts(dsm + DN_DEST + soBd[1], b0, b1);
        const float* q0 = pB[0] + 32;
        const float* q1 = pB[1] + 32;
        a0 = *(const float4*)(q0); a1 = *(const float4*)(q0 + 4);
        b0 = *(const float4*)(q1); b1 = *(const float4*)(q1 + 4);
        cvt_sts(dsm + DN_DEST + DN_SLABB + soBd[0], a0, a1);
        cvt_sts(dsm + DN_DEST + DN_SLABB + soBd[1], b0, b1);
    }

    for (int j = 0; j < DN_NP; j++) {
        CP_WAIT(1);
        __syncthreads();
        uint32_t pbr = DN_DEST + (uint32_t)(j & 1) * DN_PBUF;
        uint32_t pbw = DN_DEST + (uint32_t)((j + 1) & 1) * DN_PBUF;
        int s0 = 2 * j;
        int sn0 = s0 + 2, sn1 = s0 + 3;
        bool hn = (j + 1 < DN_NP);

        float4 na, nb, nc2, nd;
        if (hn) {
            const float* q0 = pB[0] + sn0 * 32;
            const float* q1 = pB[1] + sn0 * 32;
            na = *(const float4*)(q0); nb = *(const float4*)(q0 + 4);
            nc2 = *(const float4*)(q1); nd = *(const float4*)(q1 + 4);
        }

        DN_COMP((uint32_t)(s0 % ASTAGES) * A_STG, pbr);

        if (hn) {
            cvt_sts(dsm + pbw + soBd[0], na, nb);
            cvt_sts(dsm + pbw + soBd[1], nc2, nd);
            const float* q0 = pB[0] + sn1 * 32;
            const float* q1 = pB[1] + sn1 * 32;
            na = *(const float4*)(q0); nb = *(const float4*)(q0 + 4);
            nc2 = *(const float4*)(q1); nd = *(const float4*)(q1 + 4);
        }

        DN_COMP((uint32_t)((s0 + 1) % ASTAGES) * A_STG, pbr + DN_SLABB);

        if (hn) {
            cvt_sts(dsm + pbw + DN_SLABB + soBd[0], na, nb);
            cvt_sts(dsm + pbw + DN_SLABB + soBd[1], nc2, nd);
        }
        if (j + 2 < DN_NP) DN_A_PAIR(j + 2);
        CP_COMMIT();
    }
#undef DN_A_PAIR
#undef DN_COMP

    int g  = lane >> 2;
    int tq = lane & 3;
#pragma unroll
    for (int mi = 0; mi < 2; mi++) {
        int r0 = m0 + wM * 32 + mi * 16 + g;
        int r1 = r0 + 8;
#pragma unroll
        for (int t = 0; t < 8; t++) {
            int col = c0 + wN * 64 + t * 8 + 2 * tq;
            if (r0 < n)
                *(__half2*)&g_pair[((size_t)(off + r0)) * H_DIM + col] =
                    __floats2half2_rn(c[mi][t][0], c[mi][t][1]);
            if (r1 < n)
                *(__half2*)&g_pair[((size_t)(off + r1)) * H_DIM + col] =
                    __floats2half2_rn(c[mi][t][2], c[mi][t][3]);
        }
    }

    __syncthreads();
    if (tid == 0) { __threadfence(); atomicAdd(&g_dn_all, 1); }
}

// ---------------- reduce item: one token ----------------
__device__ void do_reduce(int t, float* __restrict__ out) {
    wait_counter(&g_dn_all, DN_ITEMS);
    int s[K_TOP];
#pragma unroll
    for (int k = 0; k < K_TOP; k++) s[k] = g_slot_of[t * K_TOP + k];
    int i = threadIdx.x;
    float acc[8] = {};
#pragma unroll
    for (int k = 0; k < K_TOP; k++) {
        uint4 v = *(const uint4*)&g_pair[(size_t)s[k] * H_DIM + i * 8];
        const __half2* h = (const __half2*)&v;
#pragma unroll
        for (int q = 0; q < 4; q++) {
            float2 f = __half22float2(h[q]);
            acc[2 * q]     += f.x;
            acc[2 * q + 1] += f.y;
        }
    }
    float4* ob = (float4*)(out + (size_t)t * H_DIM + i * 8);
    ob[0] = make_float4(acc[0], acc[1], acc[2], acc[3]);
    ob[1] = make_float4(acc[4], acc[5], acc[6], acc[7]);
}

// ---------------- persistent fused MoE kernel ----------------
__global__ __launch_bounds__(256, 2) void moe_kernel(const float* __restrict__ gw,
                                                     const float* __restrict__ uw,
                                                     const float* __restrict__ dw,
                                                     float* __restrict__ out) {
    __shared__ int s_item;
    for (;;) {
        if (threadIdx.x == 0) s_item = atomicAdd(&g_work, 1);
        __syncthreads();
        int item = s_item;
        __syncthreads();
        if (item >= TOT_ITEMS) return;

        if (item < DN_BASE) {
            int e = item / GU_PER_E;
            int r = item % GU_PER_E;
            do_gateup(e, (r & (GU_XT - 1)) * BM, (r >> 3) * BN, gw, uw);
        } else if (item < RD_BASE) {
            int it = item - DN_BASE;
            int e = it / DN_PER_E;
            int r = it % DN_PER_E;
            do_down(e, (r & (GU_XT - 1)) * BM, (r >> 3) * DN_BN, dw);
        } else {
            do_reduce(item - RD_BASE, out);
        }
    }
}

// ---------------- launch ----------------
extern "C" void kernel_launch(void* const* d_in, const int* in_sizes, int n_in,
                              void* d_out, int out_size) {
    const float* x      = (const float*)d_in[0];
    const float* gate_w = (const float*)d_in[1];
    const float* gw     = (const float*)d_in[2];
    const float* uw     = (const float*)d_in[3];
    const float* dw     = (const float*)d_in[4];
    float* out = (float*)d_out;

    float* logits = (out_size >= T_TOK * H_DIM + T_TOK * E_NUM) ? (out + (size_t)T_TOK * H_DIM)
                                                                : (float*)0;

    cudaFuncSetAttribute(moe_kernel, cudaFuncAttributeMaxDynamicSharedMemorySize, MOE_SMEM);

    zero_cnt_kernel<<<1, 32>>>();
    router_kernel<<<T_TOK / 4, 256>>>(x, gate_w, logits);
    scan_remap_kernel<<<1, 256>>>();
    moe_kernel<<<304, 256, MOE_SMEM>>>(gw, uw, dw, out);
}